// round 5
// baseline (speedup 1.0000x reference)
#include <cuda_runtime.h>
#include <math.h>

#define N_DATA 100000
#define NP     100352              // padded to 784 * 128 = 512 * 196
#define N_TILES (NP / 128)         // 784
#define NSPLIT 4
#define T2     (N_TILES / NSPLIT)  // 196 tiles per split
#define D      64
#define BQ     2048
#define QB     32                  // queries per CTA
#define PPT    16                  // points per thread
#define KNN    20

__device__ float g_dataT[D * NP];  // transposed data, dim-major
__device__ float g_pp[NP];         // ||p||^2 (1e30 for padding)
__device__ float g_candD[BQ * NSPLIT * KNN];
__device__ int   g_candI[BQ * NSPLIT * KNN];

// ---------------------------------------------------------------------------
__device__ __forceinline__ void cp_async16(void* smem, const void* gmem) {
    unsigned s = (unsigned)__cvta_generic_to_shared(smem);
    asm volatile("cp.async.cg.shared.global [%0], [%1], 16;" :: "r"(s), "l"(gmem));
}
#define CP_COMMIT() asm volatile("cp.async.commit_group;")
#define CP_WAIT1()  asm volatile("cp.async.wait_group 1;")

// ---------------------------------------------------------------------------
// Transpose data (N,64) -> dataT (64, NP), zero-pad tail points
// ---------------------------------------------------------------------------
__global__ void transpose_k(const float* __restrict__ data) {
    __shared__ float t[32][33];
    int p0 = blockIdx.x * 32, j0 = blockIdx.y * 32;
    for (int r = threadIdx.y; r < 32; r += 8) {
        int p = p0 + r;
        t[r][threadIdx.x] = (p < N_DATA) ? data[p * D + j0 + threadIdx.x] : 0.f;
    }
    __syncthreads();
    for (int r = threadIdx.y; r < 32; r += 8) {
        g_dataT[(j0 + r) * NP + p0 + threadIdx.x] = t[threadIdx.x][r];
    }
}

__global__ void pp_k() {
    int p = blockIdx.x * 256 + threadIdx.x;
    if (p >= NP) return;
    if (p >= N_DATA) { g_pp[p] = 1e30f; return; }
    float s = 0.f;
#pragma unroll
    for (int j = 0; j < D; j++) { float v = g_dataT[j * NP + p]; s += v * v; }
    g_pp[p] = s;
}

// ---------------------------------------------------------------------------
// MLP: x_dot = relu([x,t] @ W1 + b1) @ W2 + b2 ; write into out[:, 0:64]
// ---------------------------------------------------------------------------
__global__ __launch_bounds__(256) void mlp_k(
    const float* __restrict__ t, const float* __restrict__ z,
    const float* __restrict__ W1, const float* __restrict__ b1,
    const float* __restrict__ W2, const float* __restrict__ b2,
    float* __restrict__ out)
{
    __shared__ float sIn[16 * 68];
    __shared__ float sH[16 * 258];
    int tid = threadIdx.x;
    int r0 = blockIdx.x * 16;
    float tv = t[0];
    for (int i = tid; i < 16 * 65; i += 256) {
        int r = i / 65, c = i % 65;
        sIn[r * 68 + c] = (c < 64) ? z[(r0 + r) * 66 + c] : tv;
    }
    __syncthreads();
    {
        int r = tid & 15, jb = tid >> 4;
#pragma unroll
        for (int jj = 0; jj < 16; jj++) {
            int j = jb + jj * 16;
            float acc = b1[j];
#pragma unroll
            for (int i = 0; i < 65; i++) acc += sIn[r * 68 + i] * W1[i * 256 + j];
            sH[r * 258 + j] = fmaxf(acc, 0.f);
        }
    }
    __syncthreads();
    {
        int r = tid >> 4, db = tid & 15;
        int d0 = db * 4;
        float a0 = b2[d0], a1 = b2[d0 + 1], a2 = b2[d0 + 2], a3 = b2[d0 + 3];
#pragma unroll 8
        for (int j = 0; j < 256; j++) {
            float hv = sH[r * 258 + j];
            float4 w = *reinterpret_cast<const float4*>(W2 + j * 64 + d0);
            a0 += hv * w.x; a1 += hv * w.y; a2 += hv * w.z; a3 += hv * w.w;
        }
        int gq = r0 + r;
        out[gq * 66 + d0 + 0] = a0;
        out[gq * 66 + d0 + 1] = a1;
        out[gq * 66 + d0 + 2] = a2;
        out[gq * 66 + d0 + 3] = a3;
    }
}

// ---------------------------------------------------------------------------
// KNN over one split. 256 threads, 32 queries/CTA, 16 points/thread.
// q = tid>>3 (32 query groups), pg = tid&7 (8 point groups x 16 pts = 128).
// ---------------------------------------------------------------------------
struct Phase1 {
    float sD[2][D * 132];    // tile double buffer, dim-major, stride 132
    float ppT[2][128];
    float sQ[D * QB];        // queries, dim-major
    float qq[QB];
};
struct Phase2 {
    float listD[256 * KNN];
    int   listI[256 * KNN];
};
union KSmem { Phase1 p1; Phase2 p2; };

__device__ __forceinline__ void load_tile_async(KSmem& s, int buf, int tile, int tid) {
    const float* gsrc = g_dataT + tile * 128;
#pragma unroll
    for (int i = 0; i < 8; i++) {
        int idx = tid + i * 256;
        int j = idx >> 5, p4 = idx & 31;
        cp_async16(&s.p1.sD[buf][j * 132 + p4 * 4], gsrc + j * NP + p4 * 4);
    }
    if (tid < 32) cp_async16(&s.p1.ppT[buf][tid * 4], g_pp + tile * 128 + tid * 4);
}

__global__ __launch_bounds__(256, 2) void knn_k(const float* __restrict__ z)
{
    extern __shared__ char smem_raw[];
    KSmem& s = *reinterpret_cast<KSmem*>(smem_raw);
    int tid = threadIdx.x;
    int q = tid >> 3, pg = tid & 7;
    int q0 = blockIdx.x * QB;
    int split = blockIdx.y;
    int t0 = split * T2;

    load_tile_async(s, 0, t0, tid);
    CP_COMMIT();
    load_tile_async(s, 1, t0 + 1, tid);
    CP_COMMIT();

    // load 32 queries (dim-major) + ||q||^2
    for (int i = tid; i < D * QB; i += 256) {
        int qq_ = i & 31, j = i >> 5;
        s.p1.sQ[j * QB + qq_] = z[(q0 + qq_) * 66 + j];
    }
    __syncthreads();
    if (tid < QB) {
        float sum = 0.f;
#pragma unroll
        for (int j = 0; j < D; j++) { float v = s.p1.sQ[j * QB + tid]; sum += v * v; }
        s.p1.qq[tid] = sum;
    }
    __syncthreads();
    float qqv = s.p1.qq[q];

    float best[KNN]; int bestI[KNN];
#pragma unroll
    for (int k = 0; k < KNN; k++) { best[k] = 3.4e38f; bestI[k] = 0; }

    for (int tt = 0; tt < T2; tt++) {
        int buf = tt & 1;
        CP_WAIT1();
        __syncthreads();

        float acc[PPT];
#pragma unroll
        for (int i = 0; i < PPT; i++) acc[i] = 0.f;

        const float* qptr = s.p1.sQ + q;
        const float* dbase = s.p1.sD[buf] + pg * PPT;
#pragma unroll 4
        for (int j = 0; j < D; j++) {
            float qv = qptr[j * QB];
            const float* row = dbase + j * 132;
            float4 a = *reinterpret_cast<const float4*>(row);
            float4 b = *reinterpret_cast<const float4*>(row + 4);
            float4 c = *reinterpret_cast<const float4*>(row + 8);
            float4 d = *reinterpret_cast<const float4*>(row + 12);
            acc[0]  += qv * a.x;  acc[1]  += qv * a.y;
            acc[2]  += qv * a.z;  acc[3]  += qv * a.w;
            acc[4]  += qv * b.x;  acc[5]  += qv * b.y;
            acc[6]  += qv * b.z;  acc[7]  += qv * b.w;
            acc[8]  += qv * c.x;  acc[9]  += qv * c.y;
            acc[10] += qv * c.z;  acc[11] += qv * c.w;
            acc[12] += qv * d.x;  acc[13] += qv * d.y;
            acc[14] += qv * d.z;  acc[15] += qv * d.w;
        }
        int pbase = (t0 + tt) * 128 + pg * PPT;
#pragma unroll
        for (int i = 0; i < PPT; i++) {
            float sq = qqv + s.p1.ppT[buf][pg * PPT + i] - 2.f * acc[i];
            if (sq < best[KNN - 1]) {
                float cd = sq; int ci = pbase + i;
#pragma unroll
                for (int k = 0; k < KNN; k++) {
                    if (cd < best[k]) {
                        float td = best[k]; best[k] = cd; cd = td;
                        int ti = bestI[k]; bestI[k] = ci; ci = ti;
                    }
                }
            }
        }
        __syncthreads();
        if (tt + 2 < T2) load_tile_async(s, buf, t0 + tt + 2, tid);
        CP_COMMIT();
    }
    __syncthreads();

    // dump per-thread lists (aliases tile buffers — safe after sync)
#pragma unroll
    for (int k = 0; k < KNN; k++) {
        s.p2.listD[tid * KNN + k] = best[k];
        s.p2.listI[tid * KNN + k] = bestI[k];
    }
    __syncthreads();

    // 8-way merge per query -> global sorted candidate list (sq distances)
    if (tid < QB) {
        int ptr[8];
#pragma unroll
        for (int l = 0; l < 8; l++) ptr[l] = 0;
        int gbase = (q0 + tid) * (NSPLIT * KNN) + split * KNN;
        for (int o = 0; o < KNN; o++) {
            float bd = 3.5e38f; int bl = 0;
#pragma unroll
            for (int l = 0; l < 8; l++) {
                if (ptr[l] < KNN) {
                    float v = s.p2.listD[(tid * 8 + l) * KNN + ptr[l]];
                    if (v < bd) { bd = v; bl = l; }
                }
            }
            g_candD[gbase + o] = bd;
            g_candI[gbase + o] = s.p2.listI[(tid * 8 + bl) * KNN + ptr[bl]];
            ptr[bl]++;
        }
    }
}

// ---------------------------------------------------------------------------
// Final: merge NSPLIT sorted candidate lists, weights, velocity gather, metrics.
// ---------------------------------------------------------------------------
__global__ __launch_bounds__(256) void fin_k(
    const float* __restrict__ velocity, float* __restrict__ out)
{
    __shared__ float selW[16 * KNN];
    __shared__ int   selI[16 * KNN];
    __shared__ float uS[16 * 68];
    int tid = threadIdx.x;
    int q = tid >> 4, pg = tid & 15;
    int q0 = blockIdx.x * 16;

    if (tid < 16) {
        int base = (q0 + tid) * (NSPLIT * KNN);
        int ptr[NSPLIT];
#pragma unroll
        for (int l = 0; l < NSPLIT; l++) ptr[l] = 0;
        float sd[KNN]; int si[KNN];
        for (int o = 0; o < KNN; o++) {
            float bd = 3.5e38f; int bl = 0;
#pragma unroll
            for (int l = 0; l < NSPLIT; l++) {
                if (ptr[l] < KNN) {
                    float v = g_candD[base + l * KNN + ptr[l]];
                    if (v < bd) { bd = v; bl = l; }
                }
            }
            sd[o] = bd;
            si[o] = g_candI[base + bl * KNN + ptr[bl]];
            ptr[bl]++;
        }
        float d19 = sqrtf(fmaxf(sd[KNN - 1], 1e-30f));
        float h = fmaxf(d19, 1e-12f);
        float inv2h2 = 1.f / (2.f * h * h);
        float wsum = 0.f;
        float w[KNN];
#pragma unroll
        for (int o = 0; o < KNN; o++) {
            float d = sqrtf(fmaxf(sd[o], 1e-30f));
            w[o] = expf(-d * d * inv2h2);
            wsum += w[o];
        }
        float inv = 1.f / (wsum + 1e-12f);
#pragma unroll
        for (int o = 0; o < KNN; o++) {
            selW[tid * KNN + o] = w[o] * inv;
            selI[tid * KNN + o] = si[o];
        }
    }
    __syncthreads();

    {
        int d0 = pg * 4;
        float u0 = 0.f, u1 = 0.f, u2 = 0.f, u3 = 0.f;
#pragma unroll
        for (int o = 0; o < KNN; o++) {
            float w = selW[q * KNN + o];
            int idx = selI[q * KNN + o];
            float4 v = *reinterpret_cast<const float4*>(velocity + idx * 64 + d0);
            u0 += w * v.x; u1 += w * v.y; u2 += w * v.z; u3 += w * v.w;
        }
        uS[q * 68 + d0 + 0] = u0;
        uS[q * 68 + d0 + 1] = u1;
        uS[q * 68 + d0 + 2] = u2;
        uS[q * 68 + d0 + 3] = u3;
    }
    __syncthreads();

    if (tid < 16) {
        int gq = q0 + tid;
        float dot = 0.f, uu = 0.f, xx = 0.f;
#pragma unroll
        for (int d = 0; d < 64; d++) {
            float uv = uS[tid * 68 + d];
            float xv = out[gq * 66 + d];
            dot += uv * xv; uu += uv * uv; xx += xv * xv;
        }
        float nu = fmaxf(sqrtf(uu), 1e-8f);
        float nx = fmaxf(sqrtf(xx), 1e-8f);
        out[gq * 66 + 64] = 1.f - dot / (nu * nx);
        out[gq * 66 + 65] = uu - 2.f * dot + xx;
    }
}

// ---------------------------------------------------------------------------
extern "C" void kernel_launch(void* const* d_in, const int* in_sizes, int n_in,
                              void* d_out, int out_size)
{
    const float* t        = (const float*)d_in[0];
    const float* z        = (const float*)d_in[1];
    const float* data     = (const float*)d_in[2];
    const float* velocity = (const float*)d_in[3];
    const float* W1       = (const float*)d_in[4];
    const float* b1       = (const float*)d_in[5];
    const float* W2       = (const float*)d_in[6];
    const float* b2       = (const float*)d_in[7];
    float* out = (float*)d_out;

    cudaFuncSetAttribute(knn_k, cudaFuncAttributeMaxDynamicSharedMemorySize,
                         (int)sizeof(KSmem));

    dim3 tg(NP / 32, D / 32);
    transpose_k<<<tg, dim3(32, 8)>>>(data);
    pp_k<<<(NP + 255) / 256, 256>>>();
    mlp_k<<<BQ / 16, 256>>>(t, z, W1, b1, W2, b2, out);
    knn_k<<<dim3(BQ / QB, NSPLIT), 256, sizeof(KSmem)>>>(z);
    fin_k<<<BQ / 16, 256>>>(velocity, out);
}

// round 6
// speedup vs baseline: 1.4699x; 1.4699x over previous
#include <cuda_runtime.h>
#include <math.h>

#define N_DATA 100000
#define NP     100352              // 1568 * 64
#define TILE_PTS 64
#define N_TILES (NP / TILE_PTS)    // 1568
#define NSPLIT 4
#define T2     (N_TILES / NSPLIT)  // 392 tiles per split
#define D      64
#define BQ     2048
#define QB     32                  // queries per CTA
#define PPT    8                   // points per thread
#define KNN    20

__device__ float g_dataT[D * NP];  // transposed data, dim-major
__device__ float g_pp[NP];         // ||p||^2 (1e30 for padding)
__device__ float g_candD[BQ * NSPLIT * KNN];
__device__ int   g_candI[BQ * NSPLIT * KNN];

// ---------------------------------------------------------------------------
__device__ __forceinline__ void cp_async16(void* smem, const void* gmem) {
    unsigned s = (unsigned)__cvta_generic_to_shared(smem);
    asm volatile("cp.async.cg.shared.global [%0], [%1], 16;" :: "r"(s), "l"(gmem));
}
#define CP_COMMIT() asm volatile("cp.async.commit_group;")
#define CP_WAIT1()  asm volatile("cp.async.wait_group 1;")

// ---------------------------------------------------------------------------
// Transpose data (N,64) -> dataT (64, NP), zero-pad tail points
// ---------------------------------------------------------------------------
__global__ void transpose_k(const float* __restrict__ data) {
    __shared__ float t[32][33];
    int p0 = blockIdx.x * 32, j0 = blockIdx.y * 32;
    for (int r = threadIdx.y; r < 32; r += 8) {
        int p = p0 + r;
        t[r][threadIdx.x] = (p < N_DATA) ? data[p * D + j0 + threadIdx.x] : 0.f;
    }
    __syncthreads();
    for (int r = threadIdx.y; r < 32; r += 8) {
        g_dataT[(j0 + r) * NP + p0 + threadIdx.x] = t[threadIdx.x][r];
    }
}

__global__ void pp_k() {
    int p = blockIdx.x * 256 + threadIdx.x;
    if (p >= NP) return;
    if (p >= N_DATA) { g_pp[p] = 1e30f; return; }
    float s = 0.f;
#pragma unroll
    for (int j = 0; j < D; j++) { float v = g_dataT[j * NP + p]; s += v * v; }
    g_pp[p] = s;
}

// ---------------------------------------------------------------------------
// MLP: x_dot = relu([x,t] @ W1 + b1) @ W2 + b2 ; write into out[:, 0:64]
// ---------------------------------------------------------------------------
__global__ __launch_bounds__(256) void mlp_k(
    const float* __restrict__ t, const float* __restrict__ z,
    const float* __restrict__ W1, const float* __restrict__ b1,
    const float* __restrict__ W2, const float* __restrict__ b2,
    float* __restrict__ out)
{
    __shared__ float sIn[16 * 68];
    __shared__ float sH[16 * 258];
    int tid = threadIdx.x;
    int r0 = blockIdx.x * 16;
    float tv = t[0];
    for (int i = tid; i < 16 * 65; i += 256) {
        int r = i / 65, c = i % 65;
        sIn[r * 68 + c] = (c < 64) ? z[(r0 + r) * 66 + c] : tv;
    }
    __syncthreads();
    {
        int r = tid & 15, jb = tid >> 4;
#pragma unroll
        for (int jj = 0; jj < 16; jj++) {
            int j = jb + jj * 16;
            float acc = b1[j];
#pragma unroll
            for (int i = 0; i < 65; i++) acc += sIn[r * 68 + i] * W1[i * 256 + j];
            sH[r * 258 + j] = fmaxf(acc, 0.f);
        }
    }
    __syncthreads();
    {
        int r = tid >> 4, db = tid & 15;
        int d0 = db * 4;
        float a0 = b2[d0], a1 = b2[d0 + 1], a2 = b2[d0 + 2], a3 = b2[d0 + 3];
#pragma unroll 8
        for (int j = 0; j < 256; j++) {
            float hv = sH[r * 258 + j];
            float4 w = *reinterpret_cast<const float4*>(W2 + j * 64 + d0);
            a0 += hv * w.x; a1 += hv * w.y; a2 += hv * w.z; a3 += hv * w.w;
        }
        int gq = r0 + r;
        out[gq * 66 + d0 + 0] = a0;
        out[gq * 66 + d0 + 1] = a1;
        out[gq * 66 + d0 + 2] = a2;
        out[gq * 66 + d0 + 3] = a3;
    }
}

// ---------------------------------------------------------------------------
// KNN over one split. 256 threads, 32 queries/CTA, 8 points/thread, 64-pt tiles.
// q = tid>>3 (32 queries), pg = tid&7 (8 point groups x 8 pts = 64).
// Tile rows are stored DEINTERLEAVED: row = [chunkA(pg0..7)][chunkB(pg0..7)]
// where chunkA(pg) = points pg*8..pg*8+3, chunkB(pg) = pg*8+4..pg*8+7.
// => each LDS.128 hits 8 distinct 16B chunks within one 128B segment: 1 phase.
// ---------------------------------------------------------------------------
struct Phase1 {
    float sD[2][D * TILE_PTS];   // 64 rows x 64 floats (swizzled), 16KB each
    float ppT[2][TILE_PTS];
    float sQ[D * QB];            // queries, dim-major
    float qq[QB];
};
struct Phase2 {
    float listD[256 * KNN];
    int   listI[256 * KNN];
};
union KSmem { Phase1 p1; Phase2 p2; };

__device__ __forceinline__ void load_tile_async(KSmem& s, int buf, int tile, int tid) {
    const float* gsrc = g_dataT + tile * TILE_PTS;
#pragma unroll
    for (int i = 0; i < 4; i++) {
        int idx = tid + i * 256;              // 0..1023 = 64 rows x 16 chunks
        int j = idx >> 4, g = idx & 15;       // g = global 16B chunk in row
        int phys = ((g & 1) << 5) + ((g >> 1) << 2);  // deinterleave swizzle
        cp_async16(&s.p1.sD[buf][j * TILE_PTS + phys], gsrc + j * NP + g * 4);
    }
    if (tid < 16) cp_async16(&s.p1.ppT[buf][tid * 4], g_pp + tile * TILE_PTS + tid * 4);
}

__global__ __launch_bounds__(256, 2) void knn_k(const float* __restrict__ z)
{
    extern __shared__ char smem_raw[];
    KSmem& s = *reinterpret_cast<KSmem*>(smem_raw);
    int tid = threadIdx.x;
    int q = tid >> 3, pg = tid & 7;
    int q0 = blockIdx.x * QB;
    int split = blockIdx.y;
    int t0 = split * T2;

    load_tile_async(s, 0, t0, tid);
    CP_COMMIT();
    load_tile_async(s, 1, t0 + 1, tid);
    CP_COMMIT();

    // load 32 queries (dim-major) + ||q||^2
    for (int i = tid; i < D * QB; i += 256) {
        int qq_ = i & 31, j = i >> 5;
        s.p1.sQ[j * QB + qq_] = z[(q0 + qq_) * 66 + j];
    }
    __syncthreads();
    if (tid < QB) {
        float sum = 0.f;
#pragma unroll
        for (int j = 0; j < D; j++) { float v = s.p1.sQ[j * QB + tid]; sum += v * v; }
        s.p1.qq[tid] = sum;
    }
    __syncthreads();
    float qqv = s.p1.qq[q];

    float best[KNN]; int bestI[KNN];
#pragma unroll
    for (int k = 0; k < KNN; k++) { best[k] = 3.4e38f; bestI[k] = 0; }

    for (int tt = 0; tt < T2; tt++) {
        int buf = tt & 1;
        CP_WAIT1();
        __syncthreads();

        float acc[PPT];
#pragma unroll
        for (int i = 0; i < PPT; i++) acc[i] = 0.f;

        const float* qptr = s.p1.sQ + q;
        const float* dbase = s.p1.sD[buf] + pg * 4;   // chunkA at pg*4 floats
#pragma unroll 4
        for (int j = 0; j < D; j++) {
            float qv = qptr[j * QB];
            const float* row = dbase + j * TILE_PTS;
            float4 a = *reinterpret_cast<const float4*>(row);        // pts pg*8..+3
            float4 b = *reinterpret_cast<const float4*>(row + 32);   // pts pg*8+4..+7
            acc[0] += qv * a.x;  acc[1] += qv * a.y;
            acc[2] += qv * a.z;  acc[3] += qv * a.w;
            acc[4] += qv * b.x;  acc[5] += qv * b.y;
            acc[6] += qv * b.z;  acc[7] += qv * b.w;
        }
        int pbase = (t0 + tt) * TILE_PTS + pg * PPT;
#pragma unroll
        for (int i = 0; i < PPT; i++) {
            float sq = qqv + s.p1.ppT[buf][pg * PPT + i] - 2.f * acc[i];
            if (sq < best[KNN - 1]) {
                float cd = sq; int ci = pbase + i;
#pragma unroll
                for (int k = 0; k < KNN; k++) {
                    if (cd < best[k]) {
                        float td = best[k]; best[k] = cd; cd = td;
                        int ti = bestI[k]; bestI[k] = ci; ci = ti;
                    }
                }
            }
        }
        __syncthreads();
        if (tt + 2 < T2) load_tile_async(s, buf, t0 + tt + 2, tid);
        CP_COMMIT();
    }
    __syncthreads();

    // dump per-thread lists (aliases tile buffers — safe after sync)
#pragma unroll
    for (int k = 0; k < KNN; k++) {
        s.p2.listD[tid * KNN + k] = best[k];
        s.p2.listI[tid * KNN + k] = bestI[k];
    }
    __syncthreads();

    // 8-way merge per query -> global sorted candidate list (sq distances)
    if (tid < QB) {
        int ptr[8];
#pragma unroll
        for (int l = 0; l < 8; l++) ptr[l] = 0;
        int gbase = (q0 + tid) * (NSPLIT * KNN) + split * KNN;
        for (int o = 0; o < KNN; o++) {
            float bd = 3.5e38f; int bl = 0;
#pragma unroll
            for (int l = 0; l < 8; l++) {
                if (ptr[l] < KNN) {
                    float v = s.p2.listD[(tid * 8 + l) * KNN + ptr[l]];
                    if (v < bd) { bd = v; bl = l; }
                }
            }
            g_candD[gbase + o] = bd;
            g_candI[gbase + o] = s.p2.listI[(tid * 8 + bl) * KNN + ptr[bl]];
            ptr[bl]++;
        }
    }
}

// ---------------------------------------------------------------------------
// Final: merge NSPLIT sorted candidate lists, weights, velocity gather, metrics.
// ---------------------------------------------------------------------------
__global__ __launch_bounds__(256) void fin_k(
    const float* __restrict__ velocity, float* __restrict__ out)
{
    __shared__ float selW[16 * KNN];
    __shared__ int   selI[16 * KNN];
    __shared__ float uS[16 * 68];
    int tid = threadIdx.x;
    int q = tid >> 4, pg = tid & 15;
    int q0 = blockIdx.x * 16;

    if (tid < 16) {
        int base = (q0 + tid) * (NSPLIT * KNN);
        int ptr[NSPLIT];
#pragma unroll
        for (int l = 0; l < NSPLIT; l++) ptr[l] = 0;
        float sd[KNN]; int si[KNN];
        for (int o = 0; o < KNN; o++) {
            float bd = 3.5e38f; int bl = 0;
#pragma unroll
            for (int l = 0; l < NSPLIT; l++) {
                if (ptr[l] < KNN) {
                    float v = g_candD[base + l * KNN + ptr[l]];
                    if (v < bd) { bd = v; bl = l; }
                }
            }
            sd[o] = bd;
            si[o] = g_candI[base + bl * KNN + ptr[bl]];
            ptr[bl]++;
        }
        float d19 = sqrtf(fmaxf(sd[KNN - 1], 1e-30f));
        float h = fmaxf(d19, 1e-12f);
        float inv2h2 = 1.f / (2.f * h * h);
        float wsum = 0.f;
        float w[KNN];
#pragma unroll
        for (int o = 0; o < KNN; o++) {
            float d = sqrtf(fmaxf(sd[o], 1e-30f));
            w[o] = expf(-d * d * inv2h2);
            wsum += w[o];
        }
        float inv = 1.f / (wsum + 1e-12f);
#pragma unroll
        for (int o = 0; o < KNN; o++) {
            selW[tid * KNN + o] = w[o] * inv;
            selI[tid * KNN + o] = si[o];
        }
    }
    __syncthreads();

    {
        int d0 = pg * 4;
        float u0 = 0.f, u1 = 0.f, u2 = 0.f, u3 = 0.f;
#pragma unroll
        for (int o = 0; o < KNN; o++) {
            float w = selW[q * KNN + o];
            int idx = selI[q * KNN + o];
            float4 v = *reinterpret_cast<const float4*>(velocity + idx * 64 + d0);
            u0 += w * v.x; u1 += w * v.y; u2 += w * v.z; u3 += w * v.w;
        }
        uS[q * 68 + d0 + 0] = u0;
        uS[q * 68 + d0 + 1] = u1;
        uS[q * 68 + d0 + 2] = u2;
        uS[q * 68 + d0 + 3] = u3;
    }
    __syncthreads();

    if (tid < 16) {
        int gq = q0 + tid;
        float dot = 0.f, uu = 0.f, xx = 0.f;
#pragma unroll
        for (int d = 0; d < 64; d++) {
            float uv = uS[tid * 68 + d];
            float xv = out[gq * 66 + d];
            dot += uv * xv; uu += uv * uv; xx += xv * xv;
        }
        float nu = fmaxf(sqrtf(uu), 1e-8f);
        float nx = fmaxf(sqrtf(xx), 1e-8f);
        out[gq * 66 + 64] = 1.f - dot / (nu * nx);
        out[gq * 66 + 65] = uu - 2.f * dot + xx;
    }
}

// ---------------------------------------------------------------------------
extern "C" void kernel_launch(void* const* d_in, const int* in_sizes, int n_in,
                              void* d_out, int out_size)
{
    const float* t        = (const float*)d_in[0];
    const float* z        = (const float*)d_in[1];
    const float* data     = (const float*)d_in[2];
    const float* velocity = (const float*)d_in[3];
    const float* W1       = (const float*)d_in[4];
    const float* b1       = (const float*)d_in[5];
    const float* W2       = (const float*)d_in[6];
    const float* b2       = (const float*)d_in[7];
    float* out = (float*)d_out;

    cudaFuncSetAttribute(knn_k, cudaFuncAttributeMaxDynamicSharedMemorySize,
                         (int)sizeof(KSmem));

    dim3 tg(NP / 32, D / 32);
    transpose_k<<<tg, dim3(32, 8)>>>(data);
    pp_k<<<(NP + 255) / 256, 256>>>();
    mlp_k<<<BQ / 16, 256>>>(t, z, W1, b1, W2, b2, out);
    knn_k<<<dim3(BQ / QB, NSPLIT), 256, sizeof(KSmem)>>>(z);
    fin_k<<<BQ / 16, 256>>>(velocity, out);
}

// round 7
// speedup vs baseline: 3.7551x; 2.5546x over previous
#include <cuda_runtime.h>
#include <math.h>

#define N_DATA 100000
#define NP     100352              // 392 * 256 ; NSPLIT*12544
#define NSPLIT 8
#define SPLIT_PTS (NP / NSPLIT)    // 12544
#define TILE   64
#define TPS    (SPLIT_PTS / TILE)  // 196 tiles per split
#define D      64
#define BQ     2048
#define QBK    64                  // queries per screening CTA
#define KNN    20
#define NCAND  24                  // survivors per (query, split)
#define TCAND  (NSPLIT * NCAND)    // 192 per query

__device__ float g_phi[NP * D];    // tf32-rounded hi, k-permuted cols
__device__ float g_plo[NP * D];    // tf32 lo residual, k-permuted cols
__device__ float g_pp[NP];         // exact fp32 ||p||^2 (1e30 pad)
__device__ int   g_candI[BQ * TCAND];

// ---------------------------------------------------------------------------
__device__ __forceinline__ void cp_async16(void* smem, const void* gmem) {
    unsigned s = (unsigned)__cvta_generic_to_shared(smem);
    asm volatile("cp.async.cg.shared.global [%0], [%1], 16;" :: "r"(s), "l"(gmem));
}
#define CP_COMMIT() asm volatile("cp.async.commit_group;")
#define CP_WAIT0()  asm volatile("cp.async.wait_group 0;")

__device__ __forceinline__ unsigned f2u(float x) { return __float_as_uint(x); }

__device__ __forceinline__ void mma_tf32(float* c,
    unsigned a0, unsigned a1, unsigned a2, unsigned a3,
    unsigned b0, unsigned b1)
{
    asm volatile(
        "mma.sync.aligned.m16n8k8.row.col.f32.tf32.tf32.f32 "
        "{%0,%1,%2,%3}, {%4,%5,%6,%7}, {%8,%9}, {%0,%1,%2,%3};"
        : "+f"(c[0]), "+f"(c[1]), "+f"(c[2]), "+f"(c[3])
        : "r"(a0), "r"(a1), "r"(a2), "r"(a3), "r"(b0), "r"(b1));
}

__device__ __forceinline__ void ins20(float d, int idx,
                                      float* best, int* bestI, float& kth)
{
    if (d < kth) {
#pragma unroll
        for (int k = 0; k < KNN; k++) {
            if (d < best[k]) {
                float td = best[k]; best[k] = d; d = td;
                int ti = bestI[k]; bestI[k] = idx; idx = ti;
            }
        }
        kth = best[KNN - 1];
    }
}

// k-permutation inside each 8-chunk: phys = kc*8 + (k&3)*2 + ((k>>2)&1)
// so that mma fragment pairs (k, k+4) sit in adjacent floats (LDS.64-able).
__device__ __forceinline__ int kperm(int k) {
    return (k >> 3) * 8 + (k & 3) * 2 + ((k >> 2) & 1);
}

// ---------------------------------------------------------------------------
// Prep: hi/lo tf32 split of data (k-permuted, point-major) + exact ||p||^2
// ---------------------------------------------------------------------------
__global__ void prep_k(const float* __restrict__ data) {
    int p = blockIdx.x * 256 + threadIdx.x;
    if (p >= NP) return;
    float pp = 0.f;
#pragma unroll 8
    for (int k = 0; k < D; k++) {
        float x = (p < N_DATA) ? data[p * D + k] : 0.f;
        pp += x * x;
        unsigned h; asm volatile("cvt.rna.tf32.f32 %0, %1;" : "=r"(h) : "f"(x));
        float hf = __uint_as_float(h);
        float lf = x - hf;
        unsigned lu; asm volatile("cvt.rna.tf32.f32 %0, %1;" : "=r"(lu) : "f"(lf));
        int c = kperm(k);
        g_phi[p * D + c] = hf;
        g_plo[p * D + c] = __uint_as_float(lu);
    }
    g_pp[p] = (p < N_DATA) ? pp : 1e30f;
}

// ---------------------------------------------------------------------------
// MLP: x_dot = relu([x,t] @ W1 + b1) @ W2 + b2 ; write into out[:, 0:64]
// ---------------------------------------------------------------------------
__global__ __launch_bounds__(256) void mlp_k(
    const float* __restrict__ t, const float* __restrict__ z,
    const float* __restrict__ W1, const float* __restrict__ b1,
    const float* __restrict__ W2, const float* __restrict__ b2,
    float* __restrict__ out)
{
    __shared__ float sIn[16 * 68];
    __shared__ float sH[16 * 258];
    int tid = threadIdx.x;
    int r0 = blockIdx.x * 16;
    float tv = t[0];
    for (int i = tid; i < 16 * 65; i += 256) {
        int r = i / 65, c = i % 65;
        sIn[r * 68 + c] = (c < 64) ? z[(r0 + r) * 66 + c] : tv;
    }
    __syncthreads();
    {
        int r = tid & 15, jb = tid >> 4;
#pragma unroll
        for (int jj = 0; jj < 16; jj++) {
            int j = jb + jj * 16;
            float acc = b1[j];
#pragma unroll
            for (int i = 0; i < 65; i++) acc += sIn[r * 68 + i] * W1[i * 256 + j];
            sH[r * 258 + j] = fmaxf(acc, 0.f);
        }
    }
    __syncthreads();
    {
        int r = tid >> 4, db = tid & 15;
        int d0 = db * 4;
        float a0 = b2[d0], a1 = b2[d0 + 1], a2 = b2[d0 + 2], a3 = b2[d0 + 3];
#pragma unroll 8
        for (int j = 0; j < 256; j++) {
            float hv = sH[r * 258 + j];
            float4 w = *reinterpret_cast<const float4*>(W2 + j * 64 + d0);
            a0 += hv * w.x; a1 += hv * w.y; a2 += hv * w.z; a3 += hv * w.w;
        }
        int gq = r0 + r;
        out[gq * 66 + d0 + 0] = a0;
        out[gq * 66 + d0 + 1] = a1;
        out[gq * 66 + d0 + 2] = a2;
        out[gq * 66 + d0 + 3] = a3;
    }
}

// ---------------------------------------------------------------------------
// Screening: split-tf32 mma distances + fused top-k.
// CTA = 256 thr (8 warps), 64 queries, one point-split (12544 pts, 196 tiles).
// warp = (mstripe 0..3, nhalf 0..1): m16 x n32 of the 64x64 tile, 4 n-tiles.
// ---------------------------------------------------------------------------
struct ScrP1 {
    float Qh[QBK * 68]; float Ql[QBK * 68];   // queries hi/lo, row-major, pad 68
    float Bh[TILE * 68]; float Bl[TILE * 68]; // point tile hi/lo
    float Dist[QBK * 68];                     // sq distances 64q x 64p
    float PP[TILE];
    float QQ[QBK];
};
struct ScrP2 { float ld[256 * KNN]; int li[256 * KNN]; };
union ScrS { ScrP1 a; ScrP2 b; };

__device__ __forceinline__ void load_B(ScrS& s, int pbase, int tid) {
#pragma unroll
    for (int i = 0; i < 4; i++) {
        int c = tid + i * 256;                  // 1024 chunks = 64 rows x 16
        int r = c >> 4, ch = c & 15;
        cp_async16(&s.a.Bh[r * 68 + ch * 4], g_phi + (pbase + r) * D + ch * 4);
        cp_async16(&s.a.Bl[r * 68 + ch * 4], g_plo + (pbase + r) * D + ch * 4);
    }
    if (tid < 16) cp_async16(&s.a.PP[tid * 4], g_pp + pbase + tid * 4);
}

__global__ __launch_bounds__(256, 2) void scr_k(const float* __restrict__ z)
{
    extern __shared__ char sm[];
    ScrS& s = *reinterpret_cast<ScrS*>(sm);
    int tid = threadIdx.x, lane = tid & 31, warp = tid >> 5;
    int q0 = blockIdx.x * QBK;
    int split = blockIdx.y;
    int p0 = split * SPLIT_PTS;

    load_B(s, p0, tid);
    CP_COMMIT();

    // Q prep: hi/lo split, k-permuted
    for (int i = tid; i < QBK * D; i += 256) {
        int qi = i >> 6, k = i & 63;
        float x = z[(q0 + qi) * 66 + k];
        unsigned h; asm volatile("cvt.rna.tf32.f32 %0, %1;" : "=r"(h) : "f"(x));
        float hf = __uint_as_float(h);
        float lf = x - hf;
        unsigned lu; asm volatile("cvt.rna.tf32.f32 %0, %1;" : "=r"(lu) : "f"(lf));
        int c = kperm(k);
        s.a.Qh[qi * 68 + c] = hf;
        s.a.Ql[qi * 68 + c] = __uint_as_float(lu);
    }
    if (tid < QBK) {
        float sum = 0.f;
#pragma unroll 8
        for (int k = 0; k < D; k++) { float x = z[(q0 + tid) * 66 + k]; sum += x * x; }
        s.a.QQ[tid] = sum;
    }
    __syncthreads();

    int mstripe = warp >> 1, nhalf = warp & 1;
    int g = lane >> 2, tm = lane & 3;
    int r0 = mstripe * 16 + g, r1 = r0 + 8;
    float qq0 = s.a.QQ[r0], qq1 = s.a.QQ[r1];

    float best[KNN]; int bestI[KNN]; float kth = 3.4e38f;
#pragma unroll
    for (int k = 0; k < KNN; k++) { best[k] = 3.4e38f; bestI[k] = 0; }

    int sq_q = tid >> 2, sgrp = tid & 3;   // scan: 1 query x 16 points

    for (int tt = 0; tt < TPS; tt++) {
        CP_WAIT0();
        __syncthreads();                   // B/PP tile ready; Dist consumed

        float acc[4][4];
#pragma unroll
        for (int nt = 0; nt < 4; nt++)
#pragma unroll
            for (int i = 0; i < 4; i++) acc[nt][i] = 0.f;

#pragma unroll
        for (int kc = 0; kc < 8; kc++) {
            int ko = kc * 8 + 2 * tm;
            float2 ah0 = *reinterpret_cast<float2*>(&s.a.Qh[r0 * 68 + ko]);
            float2 ah1 = *reinterpret_cast<float2*>(&s.a.Qh[r1 * 68 + ko]);
            float2 al0 = *reinterpret_cast<float2*>(&s.a.Ql[r0 * 68 + ko]);
            float2 al1 = *reinterpret_cast<float2*>(&s.a.Ql[r1 * 68 + ko]);
#pragma unroll
            for (int nt = 0; nt < 4; nt++) {
                int pr = nhalf * 32 + nt * 8 + g;
                float2 bh = *reinterpret_cast<float2*>(&s.a.Bh[pr * 68 + ko]);
                float2 bl = *reinterpret_cast<float2*>(&s.a.Bl[pr * 68 + ko]);
                mma_tf32(acc[nt], f2u(ah0.x), f2u(ah1.x), f2u(ah0.y), f2u(ah1.y),
                                  f2u(bh.x), f2u(bh.y));
                mma_tf32(acc[nt], f2u(ah0.x), f2u(ah1.x), f2u(ah0.y), f2u(ah1.y),
                                  f2u(bl.x), f2u(bl.y));
                mma_tf32(acc[nt], f2u(al0.x), f2u(al1.x), f2u(al0.y), f2u(al1.y),
                                  f2u(bh.x), f2u(bh.y));
            }
        }

        // sq = qq + pp - 2*dot -> Dist
#pragma unroll
        for (int nt = 0; nt < 4; nt++) {
            int c0 = nhalf * 32 + nt * 8 + 2 * tm;
            float pp0 = s.a.PP[c0], pp1 = s.a.PP[c0 + 1];
            float2 v0 = make_float2(qq0 + pp0 - 2.f * acc[nt][0],
                                    qq0 + pp1 - 2.f * acc[nt][1]);
            float2 v1 = make_float2(qq1 + pp0 - 2.f * acc[nt][2],
                                    qq1 + pp1 - 2.f * acc[nt][3]);
            *reinterpret_cast<float2*>(&s.a.Dist[r0 * 68 + c0]) = v0;
            *reinterpret_cast<float2*>(&s.a.Dist[r1 * 68 + c0]) = v1;
        }
        __syncthreads();                   // all mma/STS done; B reusable

        if (tt + 1 < TPS) load_B(s, p0 + (tt + 1) * TILE, tid);
        CP_COMMIT();

        // scan Dist, guarded insert
        int pb = p0 + tt * TILE + sgrp * 16;
#pragma unroll
        for (int c4 = 0; c4 < 4; c4++) {
            float4 v = *reinterpret_cast<float4*>(
                &s.a.Dist[sq_q * 68 + sgrp * 16 + c4 * 4]);
            ins20(v.x, pb + c4 * 4 + 0, best, bestI, kth);
            ins20(v.y, pb + c4 * 4 + 1, best, bestI, kth);
            ins20(v.z, pb + c4 * 4 + 2, best, bestI, kth);
            ins20(v.w, pb + c4 * 4 + 3, best, bestI, kth);
        }
    }
    __syncthreads();

    // dump lists, merge 4 per query -> top-24 indices per (query, split)
#pragma unroll
    for (int k = 0; k < KNN; k++) {
        s.b.ld[tid * KNN + k] = best[k];
        s.b.li[tid * KNN + k] = bestI[k];
    }
    __syncthreads();
    if (tid < QBK) {
        int ptr[4] = {0, 0, 0, 0};
        int gbase = (q0 + tid) * TCAND + split * NCAND;
        for (int o = 0; o < NCAND; o++) {
            float bd = 3.5e38f; int bl = 0;
#pragma unroll
            for (int l = 0; l < 4; l++) {
                if (ptr[l] < KNN) {
                    float v = s.b.ld[(tid * 4 + l) * KNN + ptr[l]];
                    if (v < bd) { bd = v; bl = l; }
                }
            }
            g_candI[gbase + o] = s.b.li[(tid * 4 + bl) * KNN + ptr[bl]];
            ptr[bl]++;
        }
    }
}

// ---------------------------------------------------------------------------
// Final: exact fp32 refine of 192 candidates/query, top-20, weights, metrics.
// One warp per query, 8 queries per CTA.
// ---------------------------------------------------------------------------
__global__ __launch_bounds__(256) void fin2_k(
    const float* __restrict__ z, const float* __restrict__ data,
    const float* __restrict__ velocity, float* __restrict__ out)
{
    __shared__ float sQ[8][64];
    __shared__ float sqq[8];
    __shared__ float sCD[8][TCAND];
    __shared__ int   sCI[8][TCAND];
    __shared__ float selW[8][KNN];
    __shared__ int   selI[8][KNN];
    int tid = threadIdx.x, w = tid >> 5, l = tid & 31;
    int qi = blockIdx.x * 8 + w;

    float part = 0.f;
    for (int k = l; k < 64; k += 32) {
        float x = z[qi * 66 + k];
        sQ[w][k] = x; part += x * x;
    }
#pragma unroll
    for (int o = 16; o; o >>= 1) part += __shfl_xor_sync(0xffffffffu, part, o);
    if (l == 0) sqq[w] = part;
    __syncwarp();
    float qq = sqq[w];

#pragma unroll
    for (int j = 0; j < TCAND / 32; j++) {
        int c = l * (TCAND / 32) + j;
        int idx = g_candI[qi * TCAND + c];
        float dt = 0.f, pp = 0.f;
#pragma unroll
        for (int k4 = 0; k4 < 16; k4++) {
            float4 p = *reinterpret_cast<const float4*>(&data[idx * 64 + k4 * 4]);
            pp += p.x * p.x + p.y * p.y + p.z * p.z + p.w * p.w;
            dt += sQ[w][k4 * 4 + 0] * p.x + sQ[w][k4 * 4 + 1] * p.y
                + sQ[w][k4 * 4 + 2] * p.z + sQ[w][k4 * 4 + 3] * p.w;
        }
        sCD[w][c] = qq + pp - 2.f * dt;
        sCI[w][c] = idx;
    }
    __syncwarp();

    if (l == 0) {
        float best[KNN]; int bi[KNN]; float kth = 3.4e38f;
#pragma unroll
        for (int k = 0; k < KNN; k++) { best[k] = 3.4e38f; bi[k] = 0; }
        for (int c = 0; c < TCAND; c++) ins20(sCD[w][c], sCI[w][c], best, bi, kth);
        float d19 = sqrtf(fmaxf(best[KNN - 1], 1e-30f));
        float h = fmaxf(d19, 1e-12f);
        float inv2h2 = 1.f / (2.f * h * h);
        float ws = 0.f, wv[KNN];
#pragma unroll
        for (int o = 0; o < KNN; o++) {
            float d = sqrtf(fmaxf(best[o], 1e-30f));
            wv[o] = expf(-d * d * inv2h2);
            ws += wv[o];
        }
        float inv = 1.f / (ws + 1e-12f);
#pragma unroll
        for (int o = 0; o < KNN; o++) { selW[w][o] = wv[o] * inv; selI[w][o] = bi[o]; }
    }
    __syncwarp();

    int d0 = l * 2;
    float u0 = 0.f, u1 = 0.f;
#pragma unroll
    for (int o = 0; o < KNN; o++) {
        float wt = selW[w][o]; int idx = selI[w][o];
        float2 v = *reinterpret_cast<const float2*>(&velocity[idx * 64 + d0]);
        u0 += wt * v.x; u1 += wt * v.y;
    }
    float x0 = out[qi * 66 + d0], x1 = out[qi * 66 + d0 + 1];
    float pd = u0 * x0 + u1 * x1;
    float pu = u0 * u0 + u1 * u1;
    float px = x0 * x0 + x1 * x1;
#pragma unroll
    for (int o = 16; o; o >>= 1) {
        pd += __shfl_xor_sync(0xffffffffu, pd, o);
        pu += __shfl_xor_sync(0xffffffffu, pu, o);
        px += __shfl_xor_sync(0xffffffffu, px, o);
    }
    if (l == 0) {
        float nu = fmaxf(sqrtf(pu), 1e-8f);
        float nx = fmaxf(sqrtf(px), 1e-8f);
        out[qi * 66 + 64] = 1.f - pd / (nu * nx);
        out[qi * 66 + 65] = pu - 2.f * pd + px;
    }
}

// ---------------------------------------------------------------------------
extern "C" void kernel_launch(void* const* d_in, const int* in_sizes, int n_in,
                              void* d_out, int out_size)
{
    const float* t        = (const float*)d_in[0];
    const float* z        = (const float*)d_in[1];
    const float* data     = (const float*)d_in[2];
    const float* velocity = (const float*)d_in[3];
    const float* W1       = (const float*)d_in[4];
    const float* b1       = (const float*)d_in[5];
    const float* W2       = (const float*)d_in[6];
    const float* b2       = (const float*)d_in[7];
    float* out = (float*)d_out;

    cudaFuncSetAttribute(scr_k, cudaFuncAttributeMaxDynamicSharedMemorySize,
                         (int)sizeof(ScrS));

    prep_k<<<NP / 256, 256>>>(data);
    mlp_k<<<BQ / 16, 256>>>(t, z, W1, b1, W2, b2, out);
    scr_k<<<dim3(BQ / QBK, NSPLIT), 256, sizeof(ScrS)>>>(z);
    fin2_k<<<BQ / 8, 256>>>(z, data, velocity, out);
}